// round 2
// baseline (speedup 1.0000x reference)
#include <cuda_runtime.h>
#include <stdint.h>

#define N_NODES 100000
#define N_FEATS 256
#define OUT_DIM 64
#define NNZ_X   1280000
#define N_EDGES 1600000
#define TOT_NNZ (NNZ_X + N_EDGES)
#define NROWS2  (2 * N_NODES)

// scan config: 256 threads x 8 elems = 2048 per block
#define SCAN_BS 256
#define SCAN_EL 8
#define SCAN_CHUNK (SCAN_BS * SCAN_EL)
#define SCAN_NB ((NROWS2 + SCAN_CHUNK - 1) / SCAN_CHUNK)   // 98

// ---------------- device scratch (static, no allocation) ----------------
__device__ int   g_cnt[NROWS2];
__device__ int   g_off[NROWS2 + 1];
__device__ int   g_cur[NROWS2];
__device__ int   g_part[SCAN_NB];
__device__ int2  g_ent[TOT_NNZ];                       // packed (value_bits, col)
__device__ float g_xw[(size_t)N_NODES * OUT_DIM];      // 25.6 MB, L2-resident

// ---------------- threefry2x32 (exact JAX replica, key = (0, 42)) -------
__device__ __forceinline__ uint32_t rotl32(uint32_t x, int r) {
    return __funnelshift_l(x, x, r);
}

__device__ __forceinline__ uint2 threefry2x32_042(uint32_t x0, uint32_t x1) {
    const uint32_t k0 = 0u;
    const uint32_t k1 = 42u;
    const uint32_t k2 = 0x1BD11BDAu ^ k0 ^ k1;
    x0 += k0; x1 += k1;
#define TF_R4(a,b,c,d) \
    x0 += x1; x1 = rotl32(x1,(a)); x1 ^= x0; \
    x0 += x1; x1 = rotl32(x1,(b)); x1 ^= x0; \
    x0 += x1; x1 = rotl32(x1,(c)); x1 ^= x0; \
    x0 += x1; x1 = rotl32(x1,(d)); x1 ^= x0;
    TF_R4(13,15,26, 6);  x0 += k1; x1 += k2 + 1u;
    TF_R4(17,29,16,24);  x0 += k2; x1 += k0 + 2u;
    TF_R4(13,15,26, 6);  x0 += k0; x1 += k1 + 3u;
    TF_R4(17,29,16,24);  x0 += k1; x1 += k2 + 4u;
    TF_R4(13,15,26, 6);  x0 += k2; x1 += k0 + 5u;
#undef TF_R4
    return make_uint2(x0, x1);
}

// partitionable threefry bits for element i (size < 2^32):
// counts_hi = 0, counts_lo = i; 32-bit output = out.x ^ out.y
__device__ __forceinline__ uint32_t jax_bits_partitionable(uint32_t i) {
    uint2 r = threefry2x32_042(0u, i);
    return r.x ^ r.y;
}

// u = bitcast((bits >> 9) | 0x3f800000) - 1.0f, exactly as jax.random.uniform
__device__ __forceinline__ float bits_to_unit(uint32_t bits) {
    return __uint_as_float((bits >> 9) | 0x3f800000u) - 1.0f;
}

// ---------------- kernels ----------------------------------------------

__global__ void zero_cnt_kernel() {
    int i = blockIdx.x * blockDim.x + threadIdx.x;
    if (i < NROWS2) g_cnt[i] = 0;
}

__global__ void hist_kernel(const int* __restrict__ frow,
                            const int* __restrict__ arow) {
    int i = blockIdx.x * blockDim.x + threadIdx.x;
    if (i < NNZ_X) {
        atomicAdd(&g_cnt[frow[i]], 1);
    } else if (i < TOT_NNZ) {
        atomicAdd(&g_cnt[N_NODES + arow[i - NNZ_X]], 1);
    }
}

// block-local exclusive scan of g_cnt into g_off (no block offset yet)
__global__ __launch_bounds__(SCAN_BS) void scan1_kernel() {
    __shared__ int ws[SCAN_BS / 32];
    int tid  = threadIdx.x;
    int lane = tid & 31, wid = tid >> 5;
    int tbase = blockIdx.x * SCAN_CHUNK + tid * SCAN_EL;

    int vals[SCAN_EL];
    int s = 0;
#pragma unroll
    for (int k = 0; k < SCAN_EL; k++) {
        int idx = tbase + k;
        int v = (idx < NROWS2) ? g_cnt[idx] : 0;
        vals[k] = s;            // exclusive prefix within thread
        s += v;
    }
    // warp inclusive scan of thread sums
    int x = s;
#pragma unroll
    for (int d = 1; d < 32; d <<= 1) {
        int y = __shfl_up_sync(0xFFFFFFFFu, x, d);
        if (lane >= d) x += y;
    }
    if (lane == 31) ws[wid] = x;
    __syncthreads();
    if (tid == 0) {
        int acc = 0;
#pragma unroll
        for (int k = 0; k < SCAN_BS / 32; k++) { int t = ws[k]; ws[k] = acc; acc += t; }
        g_part[blockIdx.x] = acc;   // block total
    }
    __syncthreads();
    int thread_excl = (x - s) + ws[wid];
#pragma unroll
    for (int k = 0; k < SCAN_EL; k++) {
        int idx = tbase + k;
        if (idx < NROWS2) g_off[idx] = thread_excl + vals[k];
    }
}

// exclusive scan of the 98 block totals (single block of 128 threads)
__global__ __launch_bounds__(128) void scan2_kernel() {
    __shared__ int ws[4];
    int i = threadIdx.x;
    int lane = i & 31, wid = i >> 5;
    int v = (i < SCAN_NB) ? g_part[i] : 0;
    int x = v;
#pragma unroll
    for (int d = 1; d < 32; d <<= 1) {
        int y = __shfl_up_sync(0xFFFFFFFFu, x, d);
        if (lane >= d) x += y;
    }
    if (lane == 31) ws[wid] = x;
    __syncthreads();
    if (i == 0) {
        int acc = 0;
#pragma unroll
        for (int k = 0; k < 4; k++) { int t = ws[k]; ws[k] = acc; acc += t; }
    }
    __syncthreads();
    int excl = (x - v) + ws[wid];
    if (i < SCAN_NB) g_part[i] = excl;
}

// add block offsets; initialize cursor = offsets; write sentinel
__global__ __launch_bounds__(SCAN_BS) void scan3_kernel() {
    int tid = threadIdx.x;
    int tbase = blockIdx.x * SCAN_CHUNK + tid * SCAN_EL;
    int add = g_part[blockIdx.x];
#pragma unroll
    for (int k = 0; k < SCAN_EL; k++) {
        int idx = tbase + k;
        if (idx < NROWS2) {
            int t = g_off[idx] + add;
            g_off[idx] = t;
            g_cur[idx] = t;
        }
    }
    if (blockIdx.x == 0 && tid == 0) g_off[NROWS2] = TOT_NNZ;
}

// scatter entries into CSR order; dropout fused for X entries
__global__ void scatter_kernel(const float* __restrict__ fv,
                               const int* __restrict__ frow,
                               const int* __restrict__ fcol,
                               const float* __restrict__ av,
                               const int* __restrict__ arow,
                               const int* __restrict__ acol) {
    const float SCALE = (float)(1.0 / 0.9);
    int i = blockIdx.x * blockDim.x + threadIdx.x;
    if (i < NNZ_X) {
        uint32_t bits = jax_bits_partitionable((uint32_t)i);
        float u = bits_to_unit(bits);
        float v = fv[i];
        v = (0.9f + u >= 1.0f) ? v * SCALE : 0.0f;   // == floor(0.9+u) != 0
        int row = frow[i];
        int pos = atomicAdd(&g_cur[row], 1);
        g_ent[pos] = make_int2(__float_as_int(v), fcol[i]);
    } else if (i < TOT_NNZ) {
        int k = i - NNZ_X;
        int row = arow[k];
        int pos = atomicAdd(&g_cur[N_NODES + row], 1);
        g_ent[pos] = make_int2(__float_as_int(av[k]), acol[k]);
    }
}

// SpMM1: xw[n,:] = sum_{nnz in row n} v * W[col,:]   (one warp per row, float2/lane)
__global__ __launch_bounds__(256) void spmm1_kernel(const float* __restrict__ W) {
    int w = blockIdx.x * 8 + (threadIdx.x >> 5);
    if (w >= N_NODES) return;
    int lane = threadIdx.x & 31;
    int s = g_off[w], e = g_off[w + 1];
    float ax = 0.0f, ay = 0.0f;
    for (int p = s; p < e; p++) {
        int2 vc = __ldg(&g_ent[p]);
        float v = __int_as_float(vc.x);
        float2 kv = __ldg(reinterpret_cast<const float2*>(W + (size_t)vc.y * OUT_DIM) + lane);
        ax = fmaf(v, kv.x, ax);
        ay = fmaf(v, kv.y, ay);
    }
    reinterpret_cast<float2*>(g_xw + (size_t)w * OUT_DIM)[lane] = make_float2(ax, ay);
}

// SpMM2: out[i,:] = relu( sum_{edges (i<-j)} a * xw[j,:] )
__global__ __launch_bounds__(256) void spmm2_kernel(float* __restrict__ out) {
    int w = blockIdx.x * 8 + (threadIdx.x >> 5);
    if (w >= N_NODES) return;
    int lane = threadIdx.x & 31;
    int s = g_off[N_NODES + w], e = g_off[N_NODES + w + 1];
    float ax = 0.0f, ay = 0.0f;
    for (int p = s; p < e; p++) {
        int2 vc = __ldg(&g_ent[p]);
        float a = __int_as_float(vc.x);
        float2 xv = __ldg(reinterpret_cast<const float2*>(g_xw + (size_t)vc.y * OUT_DIM) + lane);
        ax = fmaf(a, xv.x, ax);
        ay = fmaf(a, xv.y, ay);
    }
    ax = fmaxf(ax, 0.0f);
    ay = fmaxf(ay, 0.0f);
    reinterpret_cast<float2*>(out + (size_t)w * OUT_DIM)[lane] = make_float2(ax, ay);
}

// ---------------- launch -------------------------------------------------
extern "C" void kernel_launch(void* const* d_in, const int* in_sizes, int n_in,
                              void* d_out, int out_size) {
    const float* fv   = (const float*)d_in[0];
    const float* W    = (const float*)d_in[1];
    const float* av   = (const float*)d_in[2];
    const int*   frow = (const int*)d_in[3];
    const int*   fcol = (const int*)d_in[4];
    const int*   arow = (const int*)d_in[5];
    const int*   acol = (const int*)d_in[6];
    float* out = (float*)d_out;

    zero_cnt_kernel<<<(NROWS2 + 255) / 256, 256>>>();
    hist_kernel<<<(TOT_NNZ + 255) / 256, 256>>>(frow, arow);
    scan1_kernel<<<SCAN_NB, SCAN_BS>>>();
    scan2_kernel<<<1, 128>>>();
    scan3_kernel<<<SCAN_NB, SCAN_BS>>>();
    scatter_kernel<<<(TOT_NNZ + 255) / 256, 256>>>(fv, frow, fcol, av, arow, acol);
    spmm1_kernel<<<(N_NODES + 7) / 8, 256>>>(W);
    spmm2_kernel<<<(N_NODES + 7) / 8, 256>>>(out);
}

// round 3
// speedup vs baseline: 1.0761x; 1.0761x over previous
#include <cuda_runtime.h>
#include <stdint.h>

#define N_NODES 100000
#define N_FEATS 256
#define OUT_DIM 64
#define NNZ_X   1280000
#define N_EDGES 1600000
#define TOT_NNZ (NNZ_X + N_EDGES)
#define NROWS2  (2 * N_NODES)

// scan config: 256 threads x 8 elems = 2048 per block
#define SCAN_BS 256
#define SCAN_EL 8
#define SCAN_CHUNK (SCAN_BS * SCAN_EL)
#define SCAN_NB ((NROWS2 + SCAN_CHUNK - 1) / SCAN_CHUNK)   // 98

// ---------------- device scratch (static, no allocation) ----------------
// invariant: g_cnt is all-zero on entry to kernel_launch (BSS zero on first
// call; the scan kernel re-zeroes it after consuming it on every call).
__device__ int   g_cnt[NROWS2];
__device__ int   g_off[NROWS2 + 1];
__device__ int   g_cur[NROWS2];
__device__ unsigned long long g_desc[SCAN_NB];         // (value<<32)|status
__device__ int2  g_ent[TOT_NNZ];                       // packed (value_bits, col)
__device__ float g_xw[(size_t)N_NODES * OUT_DIM];      // 25.6 MB, L2-resident

// ---------------- threefry2x32 (exact JAX replica, key = (0, 42)) -------
__device__ __forceinline__ uint32_t rotl32(uint32_t x, int r) {
    return __funnelshift_l(x, x, r);
}

__device__ __forceinline__ uint2 threefry2x32_042(uint32_t x0, uint32_t x1) {
    const uint32_t k0 = 0u;
    const uint32_t k1 = 42u;
    const uint32_t k2 = 0x1BD11BDAu ^ k0 ^ k1;
    x0 += k0; x1 += k1;
#define TF_R4(a,b,c,d) \
    x0 += x1; x1 = rotl32(x1,(a)); x1 ^= x0; \
    x0 += x1; x1 = rotl32(x1,(b)); x1 ^= x0; \
    x0 += x1; x1 = rotl32(x1,(c)); x1 ^= x0; \
    x0 += x1; x1 = rotl32(x1,(d)); x1 ^= x0;
    TF_R4(13,15,26, 6);  x0 += k1; x1 += k2 + 1u;
    TF_R4(17,29,16,24);  x0 += k2; x1 += k0 + 2u;
    TF_R4(13,15,26, 6);  x0 += k0; x1 += k1 + 3u;
    TF_R4(17,29,16,24);  x0 += k1; x1 += k2 + 4u;
    TF_R4(13,15,26, 6);  x0 += k2; x1 += k0 + 5u;
#undef TF_R4
    return make_uint2(x0, x1);
}

// partitionable threefry bits for element i: counts (0, i), out = x ^ y
__device__ __forceinline__ uint32_t jax_bits_partitionable(uint32_t i) {
    uint2 r = threefry2x32_042(0u, i);
    return r.x ^ r.y;
}

// u = bitcast((bits >> 9) | 0x3f800000) - 1.0f, exactly as jax.random.uniform
__device__ __forceinline__ float bits_to_unit(uint32_t bits) {
    return __uint_as_float((bits >> 9) | 0x3f800000u) - 1.0f;
}

__device__ __forceinline__ float dropout_val(uint32_t i, float v) {
    const float SCALE = (float)(1.0 / 0.9);
    float u = bits_to_unit(jax_bits_partitionable(i));
    return (0.9f + u >= 1.0f) ? v * SCALE : 0.0f;   // == floor(0.9+u) != 0
}

// ---------------- kernels ----------------------------------------------

// histogram rows (int4-vectorized) + clear scan descriptors for this call
#define HQ_X   (NNZ_X / 4)
#define HQ_TOT (TOT_NNZ / 4)
__global__ __launch_bounds__(256) void hist_kernel(const int* __restrict__ frow,
                                                   const int* __restrict__ arow) {
    if (blockIdx.x == 0 && threadIdx.x < SCAN_NB) g_desc[threadIdx.x] = 0ULL;
    int q = blockIdx.x * blockDim.x + threadIdx.x;
    if (q < HQ_X) {
        int4 r = __ldg(reinterpret_cast<const int4*>(frow) + q);
        atomicAdd(&g_cnt[r.x], 1);
        atomicAdd(&g_cnt[r.y], 1);
        atomicAdd(&g_cnt[r.z], 1);
        atomicAdd(&g_cnt[r.w], 1);
    } else if (q < HQ_TOT) {
        int4 r = __ldg(reinterpret_cast<const int4*>(arow) + (q - HQ_X));
        atomicAdd(&g_cnt[N_NODES + r.x], 1);
        atomicAdd(&g_cnt[N_NODES + r.y], 1);
        atomicAdd(&g_cnt[N_NODES + r.z], 1);
        atomicAdd(&g_cnt[N_NODES + r.w], 1);
    }
}

// fused single-pass exclusive scan (decoupled lookback), also:
//  - re-zeroes g_cnt for the next call
//  - initializes g_cur = g_off
//  - writes the sentinel g_off[NROWS2]
__global__ __launch_bounds__(SCAN_BS) void scan_kernel() {
    __shared__ int ws[SCAN_BS / 32];
    __shared__ int s_total;
    __shared__ unsigned s_prefix;

    int b    = blockIdx.x;
    int tid  = threadIdx.x;
    int lane = tid & 31, wid = tid >> 5;
    int tbase = b * SCAN_CHUNK + tid * SCAN_EL;

    // load 8 counts (2x int4) and zero them back
    int v[SCAN_EL];
    {
        int4 z = make_int4(0, 0, 0, 0);
#pragma unroll
        for (int h = 0; h < 2; h++) {
            int idx = tbase + h * 4;
            if (idx < NROWS2) {   // NROWS2 % 4 == 0, idx % 4 == 0 -> whole quad ok
                int4 a = *reinterpret_cast<int4*>(&g_cnt[idx]);
                *reinterpret_cast<int4*>(&g_cnt[idx]) = z;
                v[h * 4 + 0] = a.x; v[h * 4 + 1] = a.y;
                v[h * 4 + 2] = a.z; v[h * 4 + 3] = a.w;
            } else {
                v[h * 4 + 0] = v[h * 4 + 1] = v[h * 4 + 2] = v[h * 4 + 3] = 0;
            }
        }
    }

    int pre[SCAN_EL];
    int s = 0;
#pragma unroll
    for (int k = 0; k < SCAN_EL; k++) { pre[k] = s; s += v[k]; }

    // warp inclusive scan of thread sums
    int x = s;
#pragma unroll
    for (int d = 1; d < 32; d <<= 1) {
        int y = __shfl_up_sync(0xFFFFFFFFu, x, d);
        if (lane >= d) x += y;
    }
    if (lane == 31) ws[wid] = x;
    __syncthreads();
    if (tid == 0) {
        int acc = 0;
#pragma unroll
        for (int k = 0; k < SCAN_BS / 32; k++) { int t = ws[k]; ws[k] = acc; acc += t; }
        s_total = acc;
    }
    __syncthreads();

    // warp 0: publish + lookback
    if (wid == 0) {
        unsigned total = (unsigned)s_total;
        if (b == 0) {
            if (lane == 0) {
                atomicExch(&g_desc[0], ((unsigned long long)total << 32) | 2ULL);
                s_prefix = 0u;
            }
        } else {
            if (lane == 0)
                atomicExch(&g_desc[b], ((unsigned long long)total << 32) | 1ULL);
            unsigned running = 0;
            int hb = b;
            while (true) {
                int j = hb - 1 - lane;
                unsigned long long d64;
                if (j >= 0) {
                    do { d64 = atomicAdd(&g_desc[j], 0ULL); } while ((d64 & 3ULL) == 0ULL);
                } else {
                    d64 = 2ULL;   // virtual PREFIX(0) before block 0
                }
                unsigned st  = (unsigned)(d64 & 3ULL);
                unsigned val = (unsigned)(d64 >> 32);
                unsigned pm  = __ballot_sync(0xFFFFFFFFu, st == 2u);
                if (pm) {
                    int L = __ffs(pm) - 1;           // closest PREFIX
                    unsigned c = (lane <= L) ? val : 0u;
#pragma unroll
                    for (int d = 16; d; d >>= 1) c += __shfl_xor_sync(0xFFFFFFFFu, c, d);
                    running += c;
                    break;
                } else {
                    unsigned c = val;
#pragma unroll
                    for (int d = 16; d; d >>= 1) c += __shfl_xor_sync(0xFFFFFFFFu, c, d);
                    running += c;
                    hb -= 32;
                }
            }
            if (lane == 0) {
                atomicExch(&g_desc[b],
                           ((unsigned long long)(running + total) << 32) | 2ULL);
                s_prefix = running;
            }
        }
    }
    __syncthreads();

    int base = (int)s_prefix + (x - s) + ws[wid];
#pragma unroll
    for (int k = 0; k < SCAN_EL; k++) {
        int idx = tbase + k;
        if (idx < NROWS2) {
            int t = base + pre[k];
            g_off[idx] = t;
            g_cur[idx] = t;
        }
    }
    if (b == 0 && tid == 0) g_off[NROWS2] = TOT_NNZ;
}

// scatter entries into CSR order (x2 vectorized); dropout fused for X entries
#define SQ_X   (NNZ_X / 2)
#define SQ_TOT (TOT_NNZ / 2)
__global__ __launch_bounds__(256) void scatter_kernel(const float* __restrict__ fv,
                                                      const int* __restrict__ frow,
                                                      const int* __restrict__ fcol,
                                                      const float* __restrict__ av,
                                                      const int* __restrict__ arow,
                                                      const int* __restrict__ acol) {
    int q = blockIdx.x * blockDim.x + threadIdx.x;
    if (q < SQ_X) {
        float2 v2 = __ldg(reinterpret_cast<const float2*>(fv) + q);
        int2   r2 = __ldg(reinterpret_cast<const int2*>(frow) + q);
        int2   c2 = __ldg(reinterpret_cast<const int2*>(fcol) + q);
        {
            float v = dropout_val((uint32_t)(2 * q), v2.x);
            int pos = atomicAdd(&g_cur[r2.x], 1);
            g_ent[pos] = make_int2(__float_as_int(v), c2.x);
        }
        {
            float v = dropout_val((uint32_t)(2 * q + 1), v2.y);
            int pos = atomicAdd(&g_cur[r2.y], 1);
            g_ent[pos] = make_int2(__float_as_int(v), c2.y);
        }
    } else if (q < SQ_TOT) {
        int k = q - SQ_X;
        float2 v2 = __ldg(reinterpret_cast<const float2*>(av) + k);
        int2   r2 = __ldg(reinterpret_cast<const int2*>(arow) + k);
        int2   c2 = __ldg(reinterpret_cast<const int2*>(acol) + k);
        {
            int pos = atomicAdd(&g_cur[N_NODES + r2.x], 1);
            g_ent[pos] = make_int2(__float_as_int(v2.x), c2.x);
        }
        {
            int pos = atomicAdd(&g_cur[N_NODES + r2.y], 1);
            g_ent[pos] = make_int2(__float_as_int(v2.y), c2.y);
        }
    }
}

// SpMM1: xw[n,:] = sum_{nnz in row n} v * W[col,:]  (warp/row, float2/lane,
// ent loaded coalesced once per 32 nnz and broadcast via shfl)
__global__ __launch_bounds__(256) void spmm1_kernel(const float* __restrict__ W) {
    int w = blockIdx.x * 8 + (threadIdx.x >> 5);
    if (w >= N_NODES) return;
    int lane = threadIdx.x & 31;
    int s = g_off[w], e = g_off[w + 1];
    float ax = 0.0f, ay = 0.0f;
    for (int base = s; base < e; base += 32) {
        int n = min(32, e - base);
        int2 my = make_int2(0, 0);
        if (base + lane < e) my = __ldg(&g_ent[base + lane]);
        for (int k = 0; k < n; k++) {
            float v = __int_as_float(__shfl_sync(0xFFFFFFFFu, my.x, k));
            int   c = __shfl_sync(0xFFFFFFFFu, my.y, k);
            float2 kv = __ldg(reinterpret_cast<const float2*>(W + (size_t)c * OUT_DIM) + lane);
            ax = fmaf(v, kv.x, ax);
            ay = fmaf(v, kv.y, ay);
        }
    }
    reinterpret_cast<float2*>(g_xw + (size_t)w * OUT_DIM)[lane] = make_float2(ax, ay);
}

// SpMM2: out[i,:] = relu( sum_{edges (i<-j)} a * xw[j,:] )
__global__ __launch_bounds__(256) void spmm2_kernel(float* __restrict__ out) {
    int w = blockIdx.x * 8 + (threadIdx.x >> 5);
    if (w >= N_NODES) return;
    int lane = threadIdx.x & 31;
    int s = g_off[N_NODES + w], e = g_off[N_NODES + w + 1];
    float ax = 0.0f, ay = 0.0f;
    for (int base = s; base < e; base += 32) {
        int n = min(32, e - base);
        int2 my = make_int2(0, 0);
        if (base + lane < e) my = __ldg(&g_ent[base + lane]);
        for (int k = 0; k < n; k++) {
            float a = __int_as_float(__shfl_sync(0xFFFFFFFFu, my.x, k));
            int   c = __shfl_sync(0xFFFFFFFFu, my.y, k);
            float2 xv = __ldg(reinterpret_cast<const float2*>(g_xw + (size_t)c * OUT_DIM) + lane);
            ax = fmaf(a, xv.x, ax);
            ay = fmaf(a, xv.y, ay);
        }
    }
    ax = fmaxf(ax, 0.0f);
    ay = fmaxf(ay, 0.0f);
    reinterpret_cast<float2*>(out + (size_t)w * OUT_DIM)[lane] = make_float2(ax, ay);
}

// ---------------- launch -------------------------------------------------
extern "C" void kernel_launch(void* const* d_in, const int* in_sizes, int n_in,
                              void* d_out, int out_size) {
    const float* fv   = (const float*)d_in[0];
    const float* W    = (const float*)d_in[1];
    const float* av   = (const float*)d_in[2];
    const int*   frow = (const int*)d_in[3];
    const int*   fcol = (const int*)d_in[4];
    const int*   arow = (const int*)d_in[5];
    const int*   acol = (const int*)d_in[6];
    float* out = (float*)d_out;

    hist_kernel<<<(HQ_TOT + 255) / 256, 256>>>(frow, arow);
    scan_kernel<<<SCAN_NB, SCAN_BS>>>();
    scatter_kernel<<<(SQ_TOT + 255) / 256, 256>>>(fv, frow, fcol, av, arow, acol);
    spmm1_kernel<<<(N_NODES + 7) / 8, 256>>>(W);
    spmm2_kernel<<<(N_NODES + 7) / 8, 256>>>(out);
}

// round 4
// speedup vs baseline: 1.0819x; 1.0053x over previous
#include <cuda_runtime.h>
#include <cuda_fp16.h>
#include <stdint.h>

#define N_NODES 100000
#define N_FEATS 256
#define OUT_DIM 64
#define NNZ_X   1280000
#define N_EDGES 1600000
#define TOT_NNZ (NNZ_X + N_EDGES)
#define NROWS2  (2 * N_NODES)

// scan config: 256 threads x 8 elems = 2048 per block
#define SCAN_BS 256
#define SCAN_EL 8
#define SCAN_CHUNK (SCAN_BS * SCAN_EL)
#define SCAN_NB ((NROWS2 + SCAN_CHUNK - 1) / SCAN_CHUNK)   // 98

// ---------------- device scratch (static, no allocation) ----------------
// invariant: g_cnt all-zero on entry (BSS zero first call; scan re-zeroes).
__device__ int   g_cnt[NROWS2];
__device__ int   g_off[NROWS2 + 1];
__device__ int   g_cur[NROWS2];
__device__ unsigned long long g_desc[SCAN_NB];         // (value<<32)|status
__device__ int2  g_ent[TOT_NNZ];                       // packed (value_bits, col)
__device__ __align__(128) __half g_wh[N_FEATS * OUT_DIM];            // fp16 W copy
__device__ __align__(128) __half g_xw[(size_t)N_NODES * OUT_DIM];    // fp16 xw, 12.8MB

// ---------------- threefry2x32 (exact JAX replica, key = (0, 42)) -------
__device__ __forceinline__ uint32_t rotl32(uint32_t x, int r) {
    return __funnelshift_l(x, x, r);
}

__device__ __forceinline__ uint2 threefry2x32_042(uint32_t x0, uint32_t x1) {
    const uint32_t k0 = 0u;
    const uint32_t k1 = 42u;
    const uint32_t k2 = 0x1BD11BDAu ^ k0 ^ k1;
    x0 += k0; x1 += k1;
#define TF_R4(a,b,c,d) \
    x0 += x1; x1 = rotl32(x1,(a)); x1 ^= x0; \
    x0 += x1; x1 = rotl32(x1,(b)); x1 ^= x0; \
    x0 += x1; x1 = rotl32(x1,(c)); x1 ^= x0; \
    x0 += x1; x1 = rotl32(x1,(d)); x1 ^= x0;
    TF_R4(13,15,26, 6);  x0 += k1; x1 += k2 + 1u;
    TF_R4(17,29,16,24);  x0 += k2; x1 += k0 + 2u;
    TF_R4(13,15,26, 6);  x0 += k0; x1 += k1 + 3u;
    TF_R4(17,29,16,24);  x0 += k1; x1 += k2 + 4u;
    TF_R4(13,15,26, 6);  x0 += k2; x1 += k0 + 5u;
#undef TF_R4
    return make_uint2(x0, x1);
}

// partitionable threefry bits for element i: counts (0, i), out = x ^ y
__device__ __forceinline__ uint32_t jax_bits_partitionable(uint32_t i) {
    uint2 r = threefry2x32_042(0u, i);
    return r.x ^ r.y;
}

// u = bitcast((bits >> 9) | 0x3f800000) - 1.0f, exactly as jax.random.uniform
__device__ __forceinline__ float bits_to_unit(uint32_t bits) {
    return __uint_as_float((bits >> 9) | 0x3f800000u) - 1.0f;
}

__device__ __forceinline__ float dropout_val(uint32_t i, float v) {
    const float SCALE = (float)(1.0 / 0.9);
    float u = bits_to_unit(jax_bits_partitionable(i));
    return (0.9f + u >= 1.0f) ? v * SCALE : 0.0f;   // == floor(0.9+u) != 0
}

// ---------------- kernels ----------------------------------------------

// histogram rows (int4-vectorized) + clear scan descriptors + convert W->fp16.
// Grid layout: blocks [0, HB) do histogram quads; blocks [HB, HB+8) convert W.
#define HQ_X   (NNZ_X / 4)
#define HQ_TOT (TOT_NNZ / 4)
#define HB     ((HQ_TOT + 255) / 256)
#define WCONV_B 8   // 8 blocks x 256 threads x 8 elems = 16384 = N_FEATS*OUT_DIM
__global__ __launch_bounds__(256) void hist_kernel(const int* __restrict__ frow,
                                                   const int* __restrict__ arow,
                                                   const float* __restrict__ W) {
    if (blockIdx.x == 0 && threadIdx.x < SCAN_NB) g_desc[threadIdx.x] = 0ULL;
    if (blockIdx.x >= HB) {
        int t = (blockIdx.x - HB) * 256 + threadIdx.x;   // 0..2047
#pragma unroll
        for (int k = 0; k < 8; k++) {
            int i = t * 8 + k;
            g_wh[i] = __float2half(W[i]);
        }
        return;
    }
    int q = blockIdx.x * blockDim.x + threadIdx.x;
    if (q < HQ_X) {
        int4 r = __ldg(reinterpret_cast<const int4*>(frow) + q);
        atomicAdd(&g_cnt[r.x], 1);
        atomicAdd(&g_cnt[r.y], 1);
        atomicAdd(&g_cnt[r.z], 1);
        atomicAdd(&g_cnt[r.w], 1);
    } else if (q < HQ_TOT) {
        int4 r = __ldg(reinterpret_cast<const int4*>(arow) + (q - HQ_X));
        atomicAdd(&g_cnt[N_NODES + r.x], 1);
        atomicAdd(&g_cnt[N_NODES + r.y], 1);
        atomicAdd(&g_cnt[N_NODES + r.z], 1);
        atomicAdd(&g_cnt[N_NODES + r.w], 1);
    }
}

// fused single-pass exclusive scan (decoupled lookback); re-zeroes g_cnt,
// writes g_off and g_cur, writes the sentinel.
__global__ __launch_bounds__(SCAN_BS) void scan_kernel() {
    __shared__ int ws[SCAN_BS / 32];
    __shared__ int s_total;
    __shared__ unsigned s_prefix;

    int b    = blockIdx.x;
    int tid  = threadIdx.x;
    int lane = tid & 31, wid = tid >> 5;
    int tbase = b * SCAN_CHUNK + tid * SCAN_EL;

    int v[SCAN_EL];
    {
        int4 z = make_int4(0, 0, 0, 0);
#pragma unroll
        for (int h = 0; h < 2; h++) {
            int idx = tbase + h * 4;
            if (idx < NROWS2) {
                int4 a = *reinterpret_cast<int4*>(&g_cnt[idx]);
                *reinterpret_cast<int4*>(&g_cnt[idx]) = z;
                v[h * 4 + 0] = a.x; v[h * 4 + 1] = a.y;
                v[h * 4 + 2] = a.z; v[h * 4 + 3] = a.w;
            } else {
                v[h * 4 + 0] = v[h * 4 + 1] = v[h * 4 + 2] = v[h * 4 + 3] = 0;
            }
        }
    }

    int pre[SCAN_EL];
    int s = 0;
#pragma unroll
    for (int k = 0; k < SCAN_EL; k++) { pre[k] = s; s += v[k]; }

    int x = s;
#pragma unroll
    for (int d = 1; d < 32; d <<= 1) {
        int y = __shfl_up_sync(0xFFFFFFFFu, x, d);
        if (lane >= d) x += y;
    }
    if (lane == 31) ws[wid] = x;
    __syncthreads();
    if (tid == 0) {
        int acc = 0;
#pragma unroll
        for (int k = 0; k < SCAN_BS / 32; k++) { int t = ws[k]; ws[k] = acc; acc += t; }
        s_total = acc;
    }
    __syncthreads();

    if (wid == 0) {
        unsigned total = (unsigned)s_total;
        if (b == 0) {
            if (lane == 0) {
                atomicExch(&g_desc[0], ((unsigned long long)total << 32) | 2ULL);
                s_prefix = 0u;
            }
        } else {
            if (lane == 0)
                atomicExch(&g_desc[b], ((unsigned long long)total << 32) | 1ULL);
            unsigned running = 0;
            int hb = b;
            while (true) {
                int j = hb - 1 - lane;
                unsigned long long d64;
                if (j >= 0) {
                    do { d64 = atomicAdd(&g_desc[j], 0ULL); } while ((d64 & 3ULL) == 0ULL);
                } else {
                    d64 = 2ULL;
                }
                unsigned st  = (unsigned)(d64 & 3ULL);
                unsigned val = (unsigned)(d64 >> 32);
                unsigned pm  = __ballot_sync(0xFFFFFFFFu, st == 2u);
                if (pm) {
                    int L = __ffs(pm) - 1;
                    unsigned c = (lane <= L) ? val : 0u;
#pragma unroll
                    for (int d = 16; d; d >>= 1) c += __shfl_xor_sync(0xFFFFFFFFu, c, d);
                    running += c;
                    break;
                } else {
                    unsigned c = val;
#pragma unroll
                    for (int d = 16; d; d >>= 1) c += __shfl_xor_sync(0xFFFFFFFFu, c, d);
                    running += c;
                    hb -= 32;
                }
            }
            if (lane == 0) {
                atomicExch(&g_desc[b],
                           ((unsigned long long)(running + total) << 32) | 2ULL);
                s_prefix = running;
            }
        }
    }
    __syncthreads();

    int base = (int)s_prefix + (x - s) + ws[wid];
#pragma unroll
    for (int k = 0; k < SCAN_EL; k++) {
        int idx = tbase + k;
        if (idx < NROWS2) {
            int t = base + pre[k];
            g_off[idx] = t;
            g_cur[idx] = t;
        }
    }
    if (b == 0 && tid == 0) g_off[NROWS2] = TOT_NNZ;
}

// scatter entries into CSR order (x2 vectorized); dropout fused for X entries
#define SQ_X   (NNZ_X / 2)
#define SQ_TOT (TOT_NNZ / 2)
__global__ __launch_bounds__(256) void scatter_kernel(const float* __restrict__ fv,
                                                      const int* __restrict__ frow,
                                                      const int* __restrict__ fcol,
                                                      const float* __restrict__ av,
                                                      const int* __restrict__ arow,
                                                      const int* __restrict__ acol) {
    int q = blockIdx.x * blockDim.x + threadIdx.x;
    if (q < SQ_X) {
        float2 v2 = __ldg(reinterpret_cast<const float2*>(fv) + q);
        int2   r2 = __ldg(reinterpret_cast<const int2*>(frow) + q);
        int2   c2 = __ldg(reinterpret_cast<const int2*>(fcol) + q);
        {
            float v = dropout_val((uint32_t)(2 * q), v2.x);
            int pos = atomicAdd(&g_cur[r2.x], 1);
            g_ent[pos] = make_int2(__float_as_int(v), c2.x);
        }
        {
            float v = dropout_val((uint32_t)(2 * q + 1), v2.y);
            int pos = atomicAdd(&g_cur[r2.y], 1);
            g_ent[pos] = make_int2(__float_as_int(v), c2.y);
        }
    } else if (q < SQ_TOT) {
        int k = q - SQ_X;
        float2 v2 = __ldg(reinterpret_cast<const float2*>(av) + k);
        int2   r2 = __ldg(reinterpret_cast<const int2*>(arow) + k);
        int2   c2 = __ldg(reinterpret_cast<const int2*>(acol) + k);
        {
            int pos = atomicAdd(&g_cur[N_NODES + r2.x], 1);
            g_ent[pos] = make_int2(__float_as_int(v2.x), c2.x);
        }
        {
            int pos = atomicAdd(&g_cur[N_NODES + r2.y], 1);
            g_ent[pos] = make_int2(__float_as_int(v2.y), c2.y);
        }
    }
}

// SpMM1: xw[n,:] = sum v * W[c,:]  (warp/row, 2 cols/lane, fp16 W, fp32 acc)
__global__ __launch_bounds__(256) void spmm1_kernel() {
    int w = blockIdx.x * 8 + (threadIdx.x >> 5);
    if (w >= N_NODES) return;
    int lane = threadIdx.x & 31;
    int s = g_off[w], e = g_off[w + 1];
    float ax = 0.0f, ay = 0.0f;
    for (int base = s; base < e; base += 32) {
        int n = min(32, e - base);
        int2 my = make_int2(0, 0);
        if (base + lane < e) my = __ldg(&g_ent[base + lane]);
        for (int k = 0; k < n; k++) {
            float v = __int_as_float(__shfl_sync(0xFFFFFFFFu, my.x, k));
            int   c = __shfl_sync(0xFFFFFFFFu, my.y, k);
            __half2 h = __ldg(reinterpret_cast<const __half2*>(g_wh + c * OUT_DIM) + lane);
            float2 kv = __half22float2(h);
            ax = fmaf(v, kv.x, ax);
            ay = fmaf(v, kv.y, ay);
        }
    }
    reinterpret_cast<__half2*>(g_xw + (size_t)w * OUT_DIM)[lane] =
        __floats2half2_rn(ax, ay);
}

// SpMM2: out[i,:] = relu( sum a * xw[j,:] )  (fp16 xw gather: 128B/edge)
__global__ __launch_bounds__(256) void spmm2_kernel(float* __restrict__ out) {
    int w = blockIdx.x * 8 + (threadIdx.x >> 5);
    if (w >= N_NODES) return;
    int lane = threadIdx.x & 31;
    int s = g_off[N_NODES + w], e = g_off[N_NODES + w + 1];
    float ax = 0.0f, ay = 0.0f;
    for (int base = s; base < e; base += 32) {
        int n = min(32, e - base);
        int2 my = make_int2(0, 0);
        if (base + lane < e) my = __ldg(&g_ent[base + lane]);
        for (int k = 0; k < n; k++) {
            float a = __int_as_float(__shfl_sync(0xFFFFFFFFu, my.x, k));
            int   c = __shfl_sync(0xFFFFFFFFu, my.y, k);
            __half2 h = __ldg(reinterpret_cast<const __half2*>(g_xw + (size_t)c * OUT_DIM) + lane);
            float2 xv = __half22float2(h);
            ax = fmaf(a, xv.x, ax);
            ay = fmaf(a, xv.y, ay);
        }
    }
    ax = fmaxf(ax, 0.0f);
    ay = fmaxf(ay, 0.0f);
    reinterpret_cast<float2*>(out + (size_t)w * OUT_DIM)[lane] = make_float2(ax, ay);
}

// ---------------- launch -------------------------------------------------
extern "C" void kernel_launch(void* const* d_in, const int* in_sizes, int n_in,
                              void* d_out, int out_size) {
    const float* fv   = (const float*)d_in[0];
    const float* W    = (const float*)d_in[1];
    const float* av   = (const float*)d_in[2];
    const int*   frow = (const int*)d_in[3];
    const int*   fcol = (const int*)d_in[4];
    const int*   arow = (const int*)d_in[5];
    const int*   acol = (const int*)d_in[6];
    float* out = (float*)d_out;

    hist_kernel<<<HB + WCONV_B, 256>>>(frow, arow, W);
    scan_kernel<<<SCAN_NB, SCAN_BS>>>();
    scatter_kernel<<<(SQ_TOT + 255) / 256, 256>>>(fv, frow, fcol, av, arow, acol);
    spmm1_kernel<<<(N_NODES + 7) / 8, 256>>>();
    spmm2_kernel<<<(N_NODES + 7) / 8, 256>>>(out);
}

// round 5
// speedup vs baseline: 1.1425x; 1.0560x over previous
#include <cuda_runtime.h>
#include <cuda_fp16.h>
#include <stdint.h>

#define N_NODES 100000
#define N_FEATS 256
#define OUT_DIM 64
#define NNZ_X   1280000
#define N_EDGES 1600000
#define TOT_NNZ (NNZ_X + N_EDGES)
#define NROWS2  (2 * N_NODES)

// scan config: 256 threads x 8 elems = 2048 per block
#define SCAN_BS 256
#define SCAN_EL 8
#define SCAN_CHUNK (SCAN_BS * SCAN_EL)
#define SCAN_NB ((NROWS2 + SCAN_CHUNK - 1) / SCAN_CHUNK)   // 98

// ---------------- device scratch (static, no allocation) ----------------
// invariant: g_cnt all-zero on entry (BSS zero first call; scan re-zeroes).
__device__ int   g_cnt[NROWS2];
__device__ int   g_off[NROWS2 + 1];
__device__ int   g_cur[NROWS2];
__device__ unsigned long long g_desc[SCAN_NB];         // (value<<32)|status
__device__ int2  g_ent[TOT_NNZ];                       // packed (value_bits, col)
__device__ __align__(128) __half g_wh[N_FEATS * OUT_DIM];            // fp16 W copy
__device__ __align__(128) __half g_xw[(size_t)N_NODES * OUT_DIM];    // fp16 xw, 12.8MB

// ---------------- threefry2x32 (exact JAX replica, key = (0, 42)) -------
__device__ __forceinline__ uint32_t rotl32(uint32_t x, int r) {
    return __funnelshift_l(x, x, r);
}

__device__ __forceinline__ uint2 threefry2x32_042(uint32_t x0, uint32_t x1) {
    const uint32_t k0 = 0u;
    const uint32_t k1 = 42u;
    const uint32_t k2 = 0x1BD11BDAu ^ k0 ^ k1;
    x0 += k0; x1 += k1;
#define TF_R4(a,b,c,d) \
    x0 += x1; x1 = rotl32(x1,(a)); x1 ^= x0; \
    x0 += x1; x1 = rotl32(x1,(b)); x1 ^= x0; \
    x0 += x1; x1 = rotl32(x1,(c)); x1 ^= x0; \
    x0 += x1; x1 = rotl32(x1,(d)); x1 ^= x0;
    TF_R4(13,15,26, 6);  x0 += k1; x1 += k2 + 1u;
    TF_R4(17,29,16,24);  x0 += k2; x1 += k0 + 2u;
    TF_R4(13,15,26, 6);  x0 += k0; x1 += k1 + 3u;
    TF_R4(17,29,16,24);  x0 += k1; x1 += k2 + 4u;
    TF_R4(13,15,26, 6);  x0 += k2; x1 += k0 + 5u;
#undef TF_R4
    return make_uint2(x0, x1);
}

// partitionable threefry bits for element i: counts (0, i), out = x ^ y
__device__ __forceinline__ uint32_t jax_bits_partitionable(uint32_t i) {
    uint2 r = threefry2x32_042(0u, i);
    return r.x ^ r.y;
}

// u = bitcast((bits >> 9) | 0x3f800000) - 1.0f, exactly as jax.random.uniform
__device__ __forceinline__ float bits_to_unit(uint32_t bits) {
    return __uint_as_float((bits >> 9) | 0x3f800000u) - 1.0f;
}

__device__ __forceinline__ float dropout_val(uint32_t i, float v) {
    const float SCALE = (float)(1.0 / 0.9);
    float u = bits_to_unit(jax_bits_partitionable(i));
    return (0.9f + u >= 1.0f) ? v * SCALE : 0.0f;   // == floor(0.9+u) != 0
}

// ---------------- kernels ----------------------------------------------

// histogram rows (int4-vectorized) + clear scan descriptors + convert W->fp16.
#define HQ_X   (NNZ_X / 4)
#define HQ_TOT (TOT_NNZ / 4)
#define HB     ((HQ_TOT + 255) / 256)
#define WCONV_B 8   // 8 blocks x 256 threads x 8 elems = 16384 = N_FEATS*OUT_DIM
__global__ __launch_bounds__(256) void hist_kernel(const int* __restrict__ frow,
                                                   const int* __restrict__ arow,
                                                   const float* __restrict__ W) {
    if (blockIdx.x == 0 && threadIdx.x < SCAN_NB) g_desc[threadIdx.x] = 0ULL;
    if (blockIdx.x >= HB) {
        int t = (blockIdx.x - HB) * 256 + threadIdx.x;   // 0..2047
#pragma unroll
        for (int k = 0; k < 8; k++) {
            int i = t * 8 + k;
            g_wh[i] = __float2half(W[i]);
        }
        return;
    }
    int q = blockIdx.x * blockDim.x + threadIdx.x;
    if (q < HQ_X) {
        int4 r = __ldg(reinterpret_cast<const int4*>(frow) + q);
        atomicAdd(&g_cnt[r.x], 1);
        atomicAdd(&g_cnt[r.y], 1);
        atomicAdd(&g_cnt[r.z], 1);
        atomicAdd(&g_cnt[r.w], 1);
    } else if (q < HQ_TOT) {
        int4 r = __ldg(reinterpret_cast<const int4*>(arow) + (q - HQ_X));
        atomicAdd(&g_cnt[N_NODES + r.x], 1);
        atomicAdd(&g_cnt[N_NODES + r.y], 1);
        atomicAdd(&g_cnt[N_NODES + r.z], 1);
        atomicAdd(&g_cnt[N_NODES + r.w], 1);
    }
}

// fused single-pass exclusive scan (decoupled lookback); re-zeroes g_cnt,
// writes g_off and g_cur, writes the sentinel.
__global__ __launch_bounds__(SCAN_BS) void scan_kernel() {
    __shared__ int ws[SCAN_BS / 32];
    __shared__ int s_total;
    __shared__ unsigned s_prefix;

    int b    = blockIdx.x;
    int tid  = threadIdx.x;
    int lane = tid & 31, wid = tid >> 5;
    int tbase = b * SCAN_CHUNK + tid * SCAN_EL;

    int v[SCAN_EL];
    {
        int4 z = make_int4(0, 0, 0, 0);
#pragma unroll
        for (int h = 0; h < 2; h++) {
            int idx = tbase + h * 4;
            if (idx < NROWS2) {
                int4 a = *reinterpret_cast<int4*>(&g_cnt[idx]);
                *reinterpret_cast<int4*>(&g_cnt[idx]) = z;
                v[h * 4 + 0] = a.x; v[h * 4 + 1] = a.y;
                v[h * 4 + 2] = a.z; v[h * 4 + 3] = a.w;
            } else {
                v[h * 4 + 0] = v[h * 4 + 1] = v[h * 4 + 2] = v[h * 4 + 3] = 0;
            }
        }
    }

    int pre[SCAN_EL];
    int s = 0;
#pragma unroll
    for (int k = 0; k < SCAN_EL; k++) { pre[k] = s; s += v[k]; }

    int x = s;
#pragma unroll
    for (int d = 1; d < 32; d <<= 1) {
        int y = __shfl_up_sync(0xFFFFFFFFu, x, d);
        if (lane >= d) x += y;
    }
    if (lane == 31) ws[wid] = x;
    __syncthreads();
    if (tid == 0) {
        int acc = 0;
#pragma unroll
        for (int k = 0; k < SCAN_BS / 32; k++) { int t = ws[k]; ws[k] = acc; acc += t; }
        s_total = acc;
    }
    __syncthreads();

    if (wid == 0) {
        unsigned total = (unsigned)s_total;
        if (b == 0) {
            if (lane == 0) {
                atomicExch(&g_desc[0], ((unsigned long long)total << 32) | 2ULL);
                s_prefix = 0u;
            }
        } else {
            if (lane == 0)
                atomicExch(&g_desc[b], ((unsigned long long)total << 32) | 1ULL);
            unsigned running = 0;
            int hb = b;
            while (true) {
                int j = hb - 1 - lane;
                unsigned long long d64;
                if (j >= 0) {
                    do { d64 = atomicAdd(&g_desc[j], 0ULL); } while ((d64 & 3ULL) == 0ULL);
                } else {
                    d64 = 2ULL;
                }
                unsigned st  = (unsigned)(d64 & 3ULL);
                unsigned val = (unsigned)(d64 >> 32);
                unsigned pm  = __ballot_sync(0xFFFFFFFFu, st == 2u);
                if (pm) {
                    int L = __ffs(pm) - 1;
                    unsigned c = (lane <= L) ? val : 0u;
#pragma unroll
                    for (int d = 16; d; d >>= 1) c += __shfl_xor_sync(0xFFFFFFFFu, c, d);
                    running += c;
                    break;
                } else {
                    unsigned c = val;
#pragma unroll
                    for (int d = 16; d; d >>= 1) c += __shfl_xor_sync(0xFFFFFFFFu, c, d);
                    running += c;
                    hb -= 32;
                }
            }
            if (lane == 0) {
                atomicExch(&g_desc[b],
                           ((unsigned long long)(running + total) << 32) | 2ULL);
                s_prefix = running;
            }
        }
    }
    __syncthreads();

    int base = (int)s_prefix + (x - s) + ws[wid];
#pragma unroll
    for (int k = 0; k < SCAN_EL; k++) {
        int idx = tbase + k;
        if (idx < NROWS2) {
            int t = base + pre[k];
            g_off[idx] = t;
            g_cur[idx] = t;
        }
    }
    if (b == 0 && tid == 0) g_off[NROWS2] = TOT_NNZ;
}

// scatter entries into CSR order (x2 vectorized); dropout fused for X entries
#define SQ_X   (NNZ_X / 2)
#define SQ_TOT (TOT_NNZ / 2)
__global__ __launch_bounds__(256) void scatter_kernel(const float* __restrict__ fv,
                                                      const int* __restrict__ frow,
                                                      const int* __restrict__ fcol,
                                                      const float* __restrict__ av,
                                                      const int* __restrict__ arow,
                                                      const int* __restrict__ acol) {
    int q = blockIdx.x * blockDim.x + threadIdx.x;
    if (q < SQ_X) {
        float2 v2 = __ldg(reinterpret_cast<const float2*>(fv) + q);
        int2   r2 = __ldg(reinterpret_cast<const int2*>(frow) + q);
        int2   c2 = __ldg(reinterpret_cast<const int2*>(fcol) + q);
        {
            float v = dropout_val((uint32_t)(2 * q), v2.x);
            int pos = atomicAdd(&g_cur[r2.x], 1);
            g_ent[pos] = make_int2(__float_as_int(v), c2.x);
        }
        {
            float v = dropout_val((uint32_t)(2 * q + 1), v2.y);
            int pos = atomicAdd(&g_cur[r2.y], 1);
            g_ent[pos] = make_int2(__float_as_int(v), c2.y);
        }
    } else if (q < SQ_TOT) {
        int k = q - SQ_X;
        float2 v2 = __ldg(reinterpret_cast<const float2*>(av) + k);
        int2   r2 = __ldg(reinterpret_cast<const int2*>(arow) + k);
        int2   c2 = __ldg(reinterpret_cast<const int2*>(acol) + k);
        {
            int pos = atomicAdd(&g_cur[N_NODES + r2.x], 1);
            g_ent[pos] = make_int2(__float_as_int(v2.x), c2.x);
        }
        {
            int pos = atomicAdd(&g_cur[N_NODES + r2.y], 1);
            g_ent[pos] = make_int2(__float_as_int(v2.y), c2.y);
        }
    }
}

// shared body for the gather-SpMM inner loop: warp/row, 2 cols/lane (half2),
// fp32 accumulate. OOB lanes carry (v=0, c=0) so the k-loop runs in fixed
// steps of 4 with NO bounds check -> 4 independent LDGs in flight (MLP=4).
template <bool RELU>
__device__ __forceinline__ void spmm_row(const __half* __restrict__ mat,
                                         int s, int e, int lane,
                                         float& ax, float& ay) {
    for (int base = s; base < e; base += 32) {
        int2 my = make_int2(0, 0);
        if (base + lane < e) my = __ldg(&g_ent[base + lane]);
        int n = e - base; if (n > 32) n = 32;
#pragma unroll 1
        for (int k = 0; k < n; k += 4) {
            float v0, v1, v2, v3;
            int   c0, c1, c2, c3;
            v0 = __int_as_float(__shfl_sync(0xFFFFFFFFu, my.x, k + 0));
            c0 = __shfl_sync(0xFFFFFFFFu, my.y, k + 0);
            v1 = __int_as_float(__shfl_sync(0xFFFFFFFFu, my.x, k + 1));
            c1 = __shfl_sync(0xFFFFFFFFu, my.y, k + 1);
            v2 = __int_as_float(__shfl_sync(0xFFFFFFFFu, my.x, k + 2));
            c2 = __shfl_sync(0xFFFFFFFFu, my.y, k + 2);
            v3 = __int_as_float(__shfl_sync(0xFFFFFFFFu, my.x, k + 3));
            c3 = __shfl_sync(0xFFFFFFFFu, my.y, k + 3);
            __half2 h0 = __ldg(reinterpret_cast<const __half2*>(mat + (size_t)c0 * OUT_DIM) + lane);
            __half2 h1 = __ldg(reinterpret_cast<const __half2*>(mat + (size_t)c1 * OUT_DIM) + lane);
            __half2 h2 = __ldg(reinterpret_cast<const __half2*>(mat + (size_t)c2 * OUT_DIM) + lane);
            __half2 h3 = __ldg(reinterpret_cast<const __half2*>(mat + (size_t)c3 * OUT_DIM) + lane);
            float2 f0 = __half22float2(h0);
            float2 f1 = __half22float2(h1);
            float2 f2 = __half22float2(h2);
            float2 f3 = __half22float2(h3);
            ax = fmaf(v0, f0.x, ax);  ay = fmaf(v0, f0.y, ay);
            ax = fmaf(v1, f1.x, ax);  ay = fmaf(v1, f1.y, ay);
            ax = fmaf(v2, f2.x, ax);  ay = fmaf(v2, f2.y, ay);
            ax = fmaf(v3, f3.x, ax);  ay = fmaf(v3, f3.y, ay);
        }
    }
    if (RELU) { ax = fmaxf(ax, 0.0f); ay = fmaxf(ay, 0.0f); }
}

// SpMM1: xw[n,:] = sum v * W[c,:]
__global__ __launch_bounds__(256) void spmm1_kernel() {
    int w = blockIdx.x * 8 + (threadIdx.x >> 5);
    if (w >= N_NODES) return;
    int lane = threadIdx.x & 31;
    float ax = 0.0f, ay = 0.0f;
    spmm_row<false>(g_wh, g_off[w], g_off[w + 1], lane, ax, ay);
    reinterpret_cast<__half2*>(g_xw + (size_t)w * OUT_DIM)[lane] =
        __floats2half2_rn(ax, ay);
}

// SpMM2: out[i,:] = relu( sum a * xw[j,:] )
__global__ __launch_bounds__(256) void spmm2_kernel(float* __restrict__ out) {
    int w = blockIdx.x * 8 + (threadIdx.x >> 5);
    if (w >= N_NODES) return;
    int lane = threadIdx.x & 31;
    float ax = 0.0f, ay = 0.0f;
    spmm_row<true>(g_xw, g_off[N_NODES + w], g_off[N_NODES + w + 1], lane, ax, ay);
    reinterpret_cast<float2*>(out + (size_t)w * OUT_DIM)[lane] = make_float2(ax, ay);
}

// ---------------- launch -------------------------------------------------
extern "C" void kernel_launch(void* const* d_in, const int* in_sizes, int n_in,
                              void* d_out, int out_size) {
    const float* fv   = (const float*)d_in[0];
    const float* W    = (const float*)d_in[1];
    const float* av   = (const float*)d_in[2];
    const int*   frow = (const int*)d_in[3];
    const int*   fcol = (const int*)d_in[4];
    const int*   arow = (const int*)d_in[5];
    const int*   acol = (const int*)d_in[6];
    float* out = (float*)d_out;

    hist_kernel<<<HB + WCONV_B, 256>>>(frow, arow, W);
    scan_kernel<<<SCAN_NB, SCAN_BS>>>();
    scatter_kernel<<<(SQ_TOT + 255) / 256, 256>>>(fv, frow, fcol, av, arow, acol);
    spmm1_kernel<<<(N_NODES + 7) / 8, 256>>>();
    spmm2_kernel<<<(N_NODES + 7) / 8, 256>>>(out);
}

// round 6
// speedup vs baseline: 1.1770x; 1.0302x over previous
#include <cuda_runtime.h>
#include <cuda_fp16.h>
#include <stdint.h>

#define N_NODES 100000
#define N_FEATS 256
#define OUT_DIM 64
#define NNZ_X   1280000
#define N_EDGES 1600000
#define TOT_NNZ (NNZ_X + N_EDGES)
#define NROWS2  (2 * N_NODES)

// scan config: 256 threads x 8 elems = 2048 per block; per-half scan
#define SCAN_BS 256
#define SCAN_EL 8
#define SCAN_CHUNK (SCAN_BS * SCAN_EL)
#define SCANH_NB ((N_NODES + SCAN_CHUNK - 1) / SCAN_CHUNK)   // 49

// ---------------- device scratch (static, no allocation) ----------------
// invariant: g_cnt all-zero on entry (BSS zero first call; scans re-zero).
__device__ int   g_cnt[NROWS2];
__device__ int   g_off[NROWS2 + 1];
__device__ int   g_cur[NROWS2];
__device__ unsigned long long g_descX[SCANH_NB];       // (value<<32)|status
__device__ unsigned long long g_descA[SCANH_NB];
__device__ int2  g_ent[TOT_NNZ];                       // packed (value_bits, col)
__device__ __align__(128) __half g_wh[N_FEATS * OUT_DIM];            // fp16 W copy
__device__ __align__(128) __half g_xw[(size_t)N_NODES * OUT_DIM];    // fp16 xw, 12.8MB

// ---------------- threefry2x32 (exact JAX replica, key = (0, 42)) -------
__device__ __forceinline__ uint32_t rotl32(uint32_t x, int r) {
    return __funnelshift_l(x, x, r);
}

__device__ __forceinline__ uint2 threefry2x32_042(uint32_t x0, uint32_t x1) {
    const uint32_t k0 = 0u;
    const uint32_t k1 = 42u;
    const uint32_t k2 = 0x1BD11BDAu ^ k0 ^ k1;
    x0 += k0; x1 += k1;
#define TF_R4(a,b,c,d) \
    x0 += x1; x1 = rotl32(x1,(a)); x1 ^= x0; \
    x0 += x1; x1 = rotl32(x1,(b)); x1 ^= x0; \
    x0 += x1; x1 = rotl32(x1,(c)); x1 ^= x0; \
    x0 += x1; x1 = rotl32(x1,(d)); x1 ^= x0;
    TF_R4(13,15,26, 6);  x0 += k1; x1 += k2 + 1u;
    TF_R4(17,29,16,24);  x0 += k2; x1 += k0 + 2u;
    TF_R4(13,15,26, 6);  x0 += k0; x1 += k1 + 3u;
    TF_R4(17,29,16,24);  x0 += k1; x1 += k2 + 4u;
    TF_R4(13,15,26, 6);  x0 += k2; x1 += k0 + 5u;
#undef TF_R4
    return make_uint2(x0, x1);
}

__device__ __forceinline__ uint32_t jax_bits_partitionable(uint32_t i) {
    uint2 r = threefry2x32_042(0u, i);
    return r.x ^ r.y;
}

__device__ __forceinline__ float bits_to_unit(uint32_t bits) {
    return __uint_as_float((bits >> 9) | 0x3f800000u) - 1.0f;
}

__device__ __forceinline__ float dropout_val(uint32_t i, float v) {
    const float SCALE = (float)(1.0 / 0.9);
    float u = bits_to_unit(jax_bits_partitionable(i));
    return (0.9f + u >= 1.0f) ? v * SCALE : 0.0f;   // == floor(0.9+u) != 0
}

// ---------------- histograms (per half, int4-vectorized) ----------------
#define HQ_X   (NNZ_X / 4)
#define HBX    ((HQ_X + 255) / 256)
#define WCONV_B 8   // 8 blocks x 256 threads x 8 elems = 16384 = N_FEATS*OUT_DIM
__global__ __launch_bounds__(256) void histX_kernel(const int* __restrict__ frow,
                                                    const float* __restrict__ W) {
    if (blockIdx.x == 0 && threadIdx.x < SCANH_NB) g_descX[threadIdx.x] = 0ULL;
    if (blockIdx.x >= HBX) {
        int t = (blockIdx.x - HBX) * 256 + threadIdx.x;   // 0..2047
#pragma unroll
        for (int k = 0; k < 8; k++) {
            int i = t * 8 + k;
            g_wh[i] = __float2half(W[i]);
        }
        return;
    }
    int q = blockIdx.x * blockDim.x + threadIdx.x;
    if (q < HQ_X) {
        int4 r = __ldg(reinterpret_cast<const int4*>(frow) + q);
        atomicAdd(&g_cnt[r.x], 1);
        atomicAdd(&g_cnt[r.y], 1);
        atomicAdd(&g_cnt[r.z], 1);
        atomicAdd(&g_cnt[r.w], 1);
    }
}

#define HQ_A   (N_EDGES / 4)
#define HBA    ((HQ_A + 255) / 256)
__global__ __launch_bounds__(256) void histA_kernel(const int* __restrict__ arow) {
    if (blockIdx.x == 0 && threadIdx.x < SCANH_NB) g_descA[threadIdx.x] = 0ULL;
    int q = blockIdx.x * blockDim.x + threadIdx.x;
    if (q < HQ_A) {
        int4 r = __ldg(reinterpret_cast<const int4*>(arow) + q);
        atomicAdd(&g_cnt[N_NODES + r.x], 1);
        atomicAdd(&g_cnt[N_NODES + r.y], 1);
        atomicAdd(&g_cnt[N_NODES + r.z], 1);
        atomicAdd(&g_cnt[N_NODES + r.w], 1);
    }
}

// ---------------- per-half single-pass scan (decoupled lookback) --------
// half=0: rows [0, N_NODES), prefix base 0, desc=g_descX, sentinel g_off[N_NODES]=NNZ_X
// half=1: rows [N_NODES, 2N), prefix base NNZ_X, desc=g_descA, sentinel g_off[2N]=TOT_NNZ
__global__ __launch_bounds__(SCAN_BS) void scan_kernel(int half) {
    __shared__ int ws[SCAN_BS / 32];
    __shared__ int s_total;
    __shared__ unsigned s_prefix;

    unsigned long long* desc = half ? g_descA : g_descX;
    int row_base  = half ? N_NODES : 0;
    int pref_base = half ? NNZ_X : 0;

    int b    = blockIdx.x;
    int tid  = threadIdx.x;
    int lane = tid & 31, wid = tid >> 5;
    int tbase = b * SCAN_CHUNK + tid * SCAN_EL;

    int v[SCAN_EL];
    {
        int4 z = make_int4(0, 0, 0, 0);
#pragma unroll
        for (int h = 0; h < 2; h++) {
            int idx = tbase + h * 4;
            if (idx < N_NODES) {     // N_NODES % 4 == 0, idx % 4 == 0
                int4 a = *reinterpret_cast<int4*>(&g_cnt[row_base + idx]);
                *reinterpret_cast<int4*>(&g_cnt[row_base + idx]) = z;
                v[h * 4 + 0] = a.x; v[h * 4 + 1] = a.y;
                v[h * 4 + 2] = a.z; v[h * 4 + 3] = a.w;
            } else {
                v[h * 4 + 0] = v[h * 4 + 1] = v[h * 4 + 2] = v[h * 4 + 3] = 0;
            }
        }
    }

    int pre[SCAN_EL];
    int s = 0;
#pragma unroll
    for (int k = 0; k < SCAN_EL; k++) { pre[k] = s; s += v[k]; }

    int x = s;
#pragma unroll
    for (int d = 1; d < 32; d <<= 1) {
        int y = __shfl_up_sync(0xFFFFFFFFu, x, d);
        if (lane >= d) x += y;
    }
    if (lane == 31) ws[wid] = x;
    __syncthreads();
    if (tid == 0) {
        int acc = 0;
#pragma unroll
        for (int k = 0; k < SCAN_BS / 32; k++) { int t = ws[k]; ws[k] = acc; acc += t; }
        s_total = acc;
    }
    __syncthreads();

    if (wid == 0) {
        unsigned total = (unsigned)s_total;
        if (b == 0) {
            if (lane == 0) {
                atomicExch(&desc[0], ((unsigned long long)total << 32) | 2ULL);
                s_prefix = 0u;
            }
        } else {
            if (lane == 0)
                atomicExch(&desc[b], ((unsigned long long)total << 32) | 1ULL);
            unsigned running = 0;
            int hb = b;
            while (true) {
                int j = hb - 1 - lane;
                unsigned long long d64;
                if (j >= 0) {
                    do { d64 = atomicAdd(&desc[j], 0ULL); } while ((d64 & 3ULL) == 0ULL);
                } else {
                    d64 = 2ULL;
                }
                unsigned st  = (unsigned)(d64 & 3ULL);
                unsigned val = (unsigned)(d64 >> 32);
                unsigned pm  = __ballot_sync(0xFFFFFFFFu, st == 2u);
                if (pm) {
                    int L = __ffs(pm) - 1;
                    unsigned c = (lane <= L) ? val : 0u;
#pragma unroll
                    for (int d = 16; d; d >>= 1) c += __shfl_xor_sync(0xFFFFFFFFu, c, d);
                    running += c;
                    break;
                } else {
                    unsigned c = val;
#pragma unroll
                    for (int d = 16; d; d >>= 1) c += __shfl_xor_sync(0xFFFFFFFFu, c, d);
                    running += c;
                    hb -= 32;
                }
            }
            if (lane == 0) {
                atomicExch(&desc[b],
                           ((unsigned long long)(running + total) << 32) | 2ULL);
                s_prefix = running;
            }
        }
    }
    __syncthreads();

    int base = pref_base + (int)s_prefix + (x - s) + ws[wid];
#pragma unroll
    for (int k = 0; k < SCAN_EL; k++) {
        int idx = tbase + k;
        if (idx < N_NODES) {
            int t = base + pre[k];
            g_off[row_base + idx] = t;
            g_cur[row_base + idx] = t;
        }
    }
    if (b == 0 && tid == 0) {
        if (half) g_off[NROWS2] = TOT_NNZ;
        else      g_off[N_NODES] = NNZ_X;   // also written by scanA(row 0): same value
    }
}

// ---------------- scatters (per half, x2 vectorized) --------------------
#define SQ_X   (NNZ_X / 2)
__global__ __launch_bounds__(256) void scatterX_kernel(const float* __restrict__ fv,
                                                       const int* __restrict__ frow,
                                                       const int* __restrict__ fcol) {
    int q = blockIdx.x * blockDim.x + threadIdx.x;
    if (q >= SQ_X) return;
    float2 v2 = __ldg(reinterpret_cast<const float2*>(fv) + q);
    int2   r2 = __ldg(reinterpret_cast<const int2*>(frow) + q);
    int2   c2 = __ldg(reinterpret_cast<const int2*>(fcol) + q);
    {
        float v = dropout_val((uint32_t)(2 * q), v2.x);
        int pos = atomicAdd(&g_cur[r2.x], 1);
        g_ent[pos] = make_int2(__float_as_int(v), c2.x);
    }
    {
        float v = dropout_val((uint32_t)(2 * q + 1), v2.y);
        int pos = atomicAdd(&g_cur[r2.y], 1);
        g_ent[pos] = make_int2(__float_as_int(v), c2.y);
    }
}

#define SQ_A   (N_EDGES / 2)
__global__ __launch_bounds__(256) void scatterA_kernel(const float* __restrict__ av,
                                                       const int* __restrict__ arow,
                                                       const int* __restrict__ acol) {
    int q = blockIdx.x * blockDim.x + threadIdx.x;
    if (q >= SQ_A) return;
    float2 v2 = __ldg(reinterpret_cast<const float2*>(av) + q);
    int2   r2 = __ldg(reinterpret_cast<const int2*>(arow) + q);
    int2   c2 = __ldg(reinterpret_cast<const int2*>(acol) + q);
    {
        int pos = atomicAdd(&g_cur[N_NODES + r2.x], 1);
        g_ent[pos] = make_int2(__float_as_int(v2.x), c2.x);
    }
    {
        int pos = atomicAdd(&g_cur[N_NODES + r2.y], 1);
        g_ent[pos] = make_int2(__float_as_int(v2.y), c2.y);
    }
}

// ---------------- gather SpMM body (warp/row, half2/lane, fp32 acc) -----
// OOB lanes carry (v=0, c=0) so the k-loop runs in fixed steps of 4 with no
// bounds check -> 4 independent LDGs in flight.
template <bool RELU>
__device__ __forceinline__ void spmm_row(const __half* __restrict__ mat,
                                         int s, int e, int lane,
                                         float& ax, float& ay) {
    for (int base = s; base < e; base += 32) {
        int2 my = make_int2(0, 0);
        if (base + lane < e) my = __ldg(&g_ent[base + lane]);
        int n = e - base; if (n > 32) n = 32;
#pragma unroll 1
        for (int k = 0; k < n; k += 4) {
            float v0, v1, v2, v3;
            int   c0, c1, c2, c3;
            v0 = __int_as_float(__shfl_sync(0xFFFFFFFFu, my.x, k + 0));
            c0 = __shfl_sync(0xFFFFFFFFu, my.y, k + 0);
            v1 = __int_as_float(__shfl_sync(0xFFFFFFFFu, my.x, k + 1));
            c1 = __shfl_sync(0xFFFFFFFFu, my.y, k + 1);
            v2 = __int_as_float(__shfl_sync(0xFFFFFFFFu, my.x, k + 2));
            c2 = __shfl_sync(0xFFFFFFFFu, my.y, k + 2);
            v3 = __int_as_float(__shfl_sync(0xFFFFFFFFu, my.x, k + 3));
            c3 = __shfl_sync(0xFFFFFFFFu, my.y, k + 3);
            __half2 h0 = __ldg(reinterpret_cast<const __half2*>(mat + (size_t)c0 * OUT_DIM) + lane);
            __half2 h1 = __ldg(reinterpret_cast<const __half2*>(mat + (size_t)c1 * OUT_DIM) + lane);
            __half2 h2 = __ldg(reinterpret_cast<const __half2*>(mat + (size_t)c2 * OUT_DIM) + lane);
            __half2 h3 = __ldg(reinterpret_cast<const __half2*>(mat + (size_t)c3 * OUT_DIM) + lane);
            float2 f0 = __half22float2(h0);
            float2 f1 = __half22float2(h1);
            float2 f2 = __half22float2(h2);
            float2 f3 = __half22float2(h3);
            ax = fmaf(v0, f0.x, ax);  ay = fmaf(v0, f0.y, ay);
            ax = fmaf(v1, f1.x, ax);  ay = fmaf(v1, f1.y, ay);
            ax = fmaf(v2, f2.x, ax);  ay = fmaf(v2, f2.y, ay);
            ax = fmaf(v3, f3.x, ax);  ay = fmaf(v3, f3.y, ay);
        }
    }
    if (RELU) { ax = fmaxf(ax, 0.0f); ay = fmaxf(ay, 0.0f); }
}

__global__ __launch_bounds__(256) void spmm1_kernel() {
    int w = blockIdx.x * 8 + (threadIdx.x >> 5);
    if (w >= N_NODES) return;
    int lane = threadIdx.x & 31;
    float ax = 0.0f, ay = 0.0f;
    spmm_row<false>(g_wh, g_off[w], g_off[w + 1], lane, ax, ay);
    reinterpret_cast<__half2*>(g_xw + (size_t)w * OUT_DIM)[lane] =
        __floats2half2_rn(ax, ay);
}

__global__ __launch_bounds__(256) void spmm2_kernel(float* __restrict__ out) {
    int w = blockIdx.x * 8 + (threadIdx.x >> 5);
    if (w >= N_NODES) return;
    int lane = threadIdx.x & 31;
    float ax = 0.0f, ay = 0.0f;
    spmm_row<true>(g_xw, g_off[N_NODES + w], g_off[N_NODES + w + 1], lane, ax, ay);
    reinterpret_cast<float2*>(out + (size_t)w * OUT_DIM)[lane] = make_float2(ax, ay);
}

// ---------------- launch (fork/join: A-chain on side stream) ------------
extern "C" void kernel_launch(void* const* d_in, const int* in_sizes, int n_in,
                              void* d_out, int out_size) {
    const float* fv   = (const float*)d_in[0];
    const float* W    = (const float*)d_in[1];
    const float* av   = (const float*)d_in[2];
    const int*   frow = (const int*)d_in[3];
    const int*   fcol = (const int*)d_in[4];
    const int*   arow = (const int*)d_in[5];
    const int*   acol = (const int*)d_in[6];
    float* out = (float*)d_out;

    // created once on the first (uncaptured) correctness call; reused after.
    static cudaStream_t s1 = nullptr;
    static cudaEvent_t  e_fork = nullptr, e_join = nullptr;
    if (s1 == nullptr) {
        cudaStreamCreateWithFlags(&s1, cudaStreamNonBlocking);
        cudaEventCreateWithFlags(&e_fork, cudaEventDisableTiming);
        cudaEventCreateWithFlags(&e_join, cudaEventDisableTiming);
    }

    // fork: A-chain on s1, X-chain on the launch stream
    cudaEventRecord(e_fork, 0);
    cudaStreamWaitEvent(s1, e_fork, 0);

    histX_kernel<<<HBX + WCONV_B, 256>>>(frow, W);
    histA_kernel<<<HBA, 256, 0, s1>>>(arow);

    scan_kernel<<<SCANH_NB, SCAN_BS>>>(0);
    scan_kernel<<<SCANH_NB, SCAN_BS, 0, s1>>>(1);

    scatterX_kernel<<<(SQ_X + 255) / 256, 256>>>(fv, frow, fcol);
    scatterA_kernel<<<(SQ_A + 255) / 256, 256, 0, s1>>>(av, arow, acol);
    cudaEventRecord(e_join, s1);

    spmm1_kernel<<<(N_NODES + 7) / 8, 256>>>();

    // join: spmm2 needs xw (stream 0) and adj CSR (s1)
    cudaStreamWaitEvent(0, e_join, 0);
    spmm2_kernel<<<(N_NODES + 7) / 8, 256>>>(out);
}